// round 15
// baseline (speedup 1.0000x reference)
#include <cuda_runtime.h>

#define BB 8192
#define FF 32
#define EE 64
#define PP 496   // 32 choose 2

__global__ __launch_bounds__(256)
void bilinear_pair_kernel(const float* __restrict__ x,
                          const float* __restrict__ W,
                          float* __restrict__ out)
{
    __shared__ float Ws[EE * EE];    // 16 KB  W[e*64+d]
    __shared__ float xs[FF * EE];    // 8 KB   x[b][f*64+e]
    __shared__ float xws[FF * EE];   // 8 KB   (x[b] @ W)

    const int b   = blockIdx.x;
    const int tid = threadIdx.x;

    // ---- load W (4096 floats) and x[b] (2048 floats) as float4 ----
    {
        const float4* W4  = (const float4*)W;
        float4*       Ws4 = (float4*)Ws;
        #pragma unroll
        for (int k = tid; k < EE * EE / 4; k += 256)
            Ws4[k] = W4[k];

        const float4* x4  = (const float4*)(x + (size_t)b * FF * EE);
        float4*       xs4 = (float4*)xs;
        #pragma unroll
        for (int k = tid; k < FF * EE / 4; k += 256)
            xs4[k] = x4[k];
    }
    __syncthreads();

    // ---- matmul: thread = 2 rows x 4 cols register tile ----
    // per e: 2 broadcast scalar LDS + 1 conflict-free LDS.128, 8 FMA
    {
        const int r0 = (tid >> 4) * 2;       // rows r0, r0+1
        const int c4 = (tid & 15) * 4;       // cols c4..c4+3
        float4 acc0 = make_float4(0.f, 0.f, 0.f, 0.f);
        float4 acc1 = make_float4(0.f, 0.f, 0.f, 0.f);

        #pragma unroll 16
        for (int e = 0; e < EE; e++) {
            float4 w = *(const float4*)(Ws + e * EE + c4);
            float  a0 = xs[r0 * EE + e];
            float  a1 = xs[(r0 + 1) * EE + e];
            acc0.x = fmaf(a0, w.x, acc0.x);
            acc0.y = fmaf(a0, w.y, acc0.y);
            acc0.z = fmaf(a0, w.z, acc0.z);
            acc0.w = fmaf(a0, w.w, acc0.w);
            acc1.x = fmaf(a1, w.x, acc1.x);
            acc1.y = fmaf(a1, w.y, acc1.y);
            acc1.z = fmaf(a1, w.z, acc1.z);
            acc1.w = fmaf(a1, w.w, acc1.w);
        }
        *(float4*)(xws + r0 * EE + c4)       = acc0;
        *(float4*)(xws + (r0 + 1) * EE + c4) = acc1;
    }
    __syncthreads();

    // ---- store 496 pairs: warp w owns i-strips {w, 15-w, 16+w, 31-w} (62 pairs) ----
    {
        const int wid  = tid >> 5;
        const int lane = tid & 31;
        const int half = lane >> 4;          // which j parity this half-warp handles
        const int cv   = (lane & 15) * 4;    // float offset of this lane's 16B chunk
        float* outb = out + (size_t)b * PP * EE;

        #pragma unroll
        for (int s = 0; s < 4; s++) {
            const int i = (s == 0) ? wid
                        : (s == 1) ? 15 - wid
                        : (s == 2) ? 16 + wid
                        :            31 - wid;
            if (i >= FF - 1) continue;       // i=31 has no pairs
            const int pbase = i * (63 - i) / 2;
            // loop-invariant left operand: xw[i], this lane's 16B chunk
            const float4 a = *(const float4*)(xws + i * EE + cv);

            #pragma unroll 4
            for (int j = i + 1 + half; j < FF; j += 2) {
                float4 c = *(const float4*)(xs + j * EE + cv);
                float4 r;
                r.x = a.x * c.x;
                r.y = a.y * c.y;
                r.z = a.z * c.z;
                r.w = a.w * c.w;
                const int p = pbase + (j - i - 1);
                // streaming store: 1 GB output, zero reuse — evict-first
                __stcs((float4*)(outb + (size_t)p * EE + cv), r);
            }
        }
    }
}

extern "C" void kernel_launch(void* const* d_in, const int* in_sizes, int n_in,
                              void* d_out, int out_size)
{
    const float* x = (const float*)d_in[0];
    const float* W = (const float*)d_in[1];
    float*       o = (float*)d_out;
    bilinear_pair_kernel<<<BB, 256>>>(x, W, o);
}